// round 2
// baseline (speedup 1.0000x reference)
#include <cuda_runtime.h>

// ScaledDotProductAttention, reference semantics:
//   s = (q·k)/sqrt(64) ; s[mask]=0 ; e=exp(s) ; attn=e/rowsum(e) ; out=attn·v
// Masked slots contribute exp(0)=1 to BOTH numerator and denominator, and
// there is no max-subtraction -> simple streaming accumulation, no rescale.
//
// The mask arrives as jax bool widened by the harness to an unknown encoding:
//   u8 bytes (0/1), int32 words (0/1), or float32 words (0.0/1.0).
// A 1-thread detect kernel classifies the encoding once; the main kernel's
// mask loader branches (uniformly) on the result.

#define BQ 64
#define BK 64
#define DH 64
#define LQ 2048
#define LK 2048
#define NTHREADS 256
#define NTILES (LK / BK)

__device__ int g_mask_words;   // 0 = u8 bytes, 1 = 4-byte words (int32/float32)

__global__ void detect_mask_kernel(const unsigned int* __restrict__ m) {
    // Safe to read 4096 words under every encoding (min alloc = N bytes = N/4 words,
    // N = 67M). 4-byte encodings only ever contain {0, 1, 0x3F800000}; packed-u8
    // words contain multi-byte patterns (e.g. 0x01010101) almost surely.
    int words = 1;
    for (int i = 0; i < 4096; i++) {
        unsigned int w = m[i];
        if (w != 0u && w != 1u && w != 0x3F800000u) { words = 0; break; }
    }
    g_mask_words = words;
}

__global__ void __launch_bounds__(NTHREADS, 2)
attn_fp32_kernel(const float* __restrict__ Q, const float* __restrict__ K,
                 const float* __restrict__ V, const void* __restrict__ Mraw,
                 float* __restrict__ O) {
    extern __shared__ float sm[];
    float* Qs = sm;                               // [BQ][DH]  row-major
    float* Kt = Qs + BQ * DH;                     // [DH][BK]  transposed (d-major)
    float* Vs = Kt + DH * BK;                     // [BK][DH]  row-major
    float* Ps = Vs + BK * DH;                     // [BQ][BK]  exp(scores)
    float* den = Ps + BQ * BK;                    // [BQ]
    unsigned char* Ms = (unsigned char*)(den + BQ); // [BQ][BK]

    const int tid = threadIdx.x;
    const int b  = blockIdx.y;
    const int q0 = blockIdx.x * BQ;
    const int r = (tid >> 4) << 2;   // this thread's 4 q-rows  (0..60)
    const int c = (tid & 15) << 2;   // this thread's 4 cols    (0..60)
    const int mask_words = g_mask_words;

    const float* Qb = Q + ((size_t)b * LQ + q0) * DH;
    const float* Kb = K + (size_t)b * LK * DH;
    const float* Vb = V + (size_t)b * LK * DH;
    const size_t mbase = ((size_t)b * LQ + q0) * (size_t)LK;

    // ---- load Q tile (coalesced float4) ----
    {
        int row = tid >> 2;
        int c0  = (tid & 3) << 4;
        #pragma unroll
        for (int u = 0; u < 4; u++) {
            *(float4*)&Qs[row * DH + c0 + 4 * u] =
                *(const float4*)(Qb + (size_t)row * DH + c0 + 4 * u);
        }
    }
    if (tid < BQ) den[tid] = 0.0f;

    float oacc[4][4];
    #pragma unroll
    for (int i = 0; i < 4; i++)
        #pragma unroll
        for (int j = 0; j < 4; j++) oacc[i][j] = 0.0f;

    for (int kt = 0; kt < NTILES; kt++) {
        __syncthreads();   // previous tile's consumers done (Ps/Kt/Vs/den)

        // ---- load K (transposed), V (straight) ----
        {
            int kk = tid & 63;            // key index within tile
            int d0 = (tid >> 6) << 4;     // 0,16,32,48
            const float* krow = Kb + (size_t)(kt * BK + kk) * DH + d0;
            const float* vrow = Vb + (size_t)(kt * BK + kk) * DH + d0;
            #pragma unroll
            for (int u = 0; u < 4; u++) {
                float4 kv = *(const float4*)(krow + 4 * u);
                Kt[(d0 + 4 * u + 0) * BK + kk] = kv.x;
                Kt[(d0 + 4 * u + 1) * BK + kk] = kv.y;
                Kt[(d0 + 4 * u + 2) * BK + kk] = kv.z;
                Kt[(d0 + 4 * u + 3) * BK + kk] = kv.w;
                *(float4*)&Vs[kk * DH + d0 + 4 * u] = *(const float4*)(vrow + 4 * u);
            }
        }

        // ---- load mask tile -> canonical u8 in SMEM ----
        {
            int qrow = tid >> 2;          // 0..63
            int c16  = (tid & 3) << 4;    // 0,16,32,48
            size_t elem = mbase + (size_t)qrow * LK + kt * BK + c16;
            if (mask_words) {
                const uint4* src = (const uint4*)((const unsigned int*)Mraw + elem);
                #pragma unroll
                for (int u = 0; u < 4; u++) {
                    uint4 w = src[u];
                    unsigned int packed = (w.x != 0u ? 1u : 0u)
                                        | (w.y != 0u ? 0x100u : 0u)
                                        | (w.z != 0u ? 0x10000u : 0u)
                                        | (w.w != 0u ? 0x1000000u : 0u);
                    *(unsigned int*)&Ms[qrow * BK + c16 + 4 * u] = packed;
                }
            } else {
                *(int4*)&Ms[qrow * BK + c16] =
                    *(const int4*)((const unsigned char*)Mraw + elem);
            }
        }
        __syncthreads();

        // ---- S = Q · K^T  (4x4 per thread, fp32) ----
        float s[4][4];
        #pragma unroll
        for (int i = 0; i < 4; i++)
            #pragma unroll
            for (int j = 0; j < 4; j++) s[i][j] = 0.0f;

        #pragma unroll
        for (int kk4 = 0; kk4 < DH; kk4 += 4) {
            float a_[4][4];   // [i][kk]
            float b_[4][4];   // [kk][j]
            #pragma unroll
            for (int i = 0; i < 4; i++)
                *(float4*)a_[i] = *(float4*)&Qs[(r + i) * DH + kk4];
            #pragma unroll
            for (int kk = 0; kk < 4; kk++)
                *(float4*)b_[kk] = *(float4*)&Kt[(kk4 + kk) * BK + c];
            #pragma unroll
            for (int kk = 0; kk < 4; kk++)
                #pragma unroll
                for (int i = 0; i < 4; i++)
                    #pragma unroll
                    for (int j = 0; j < 4; j++)
                        s[i][j] += a_[i][kk] * b_[kk][j];
        }

        // ---- p = mask ? 1 : exp(s / 8) ; write Ps ----
        #pragma unroll
        for (int i = 0; i < 4; i++) {
            unsigned int mw = *(unsigned int*)&Ms[(r + i) * BK + c]; // 4 mask bytes
            float p_[4];
            #pragma unroll
            for (int j = 0; j < 4; j++) {
                unsigned char mj = (mw >> (8 * j)) & 0xFF;
                p_[j] = mj ? 1.0f : __expf(s[i][j] * 0.125f);
            }
            *(float4*)&Ps[(r + i) * BK + c] = *(float4*)p_;
        }
        __syncthreads();

        // ---- denominator row-sums (threads 0..63) ----
        if (tid < BQ) {
            float sum = 0.0f;
            #pragma unroll
            for (int x = 0; x < BK; x += 4) {
                float4 pv = *(float4*)&Ps[tid * BK + x];
                sum += pv.x + pv.y + pv.z + pv.w;
            }
            den[tid] += sum;
        }

        // ---- O += P · V  (4x4 per thread) ----
        #pragma unroll
        for (int k4 = 0; k4 < BK; k4 += 4) {
            float a_[4][4];   // [i][kk]  P values
            float b_[4][4];   // [kk][j]  V values
            #pragma unroll
            for (int i = 0; i < 4; i++)
                *(float4*)a_[i] = *(float4*)&Ps[(r + i) * BK + k4];
            #pragma unroll
            for (int kk = 0; kk < 4; kk++)
                *(float4*)b_[kk] = *(float4*)&Vs[(k4 + kk) * DH + c];
            #pragma unroll
            for (int kk = 0; kk < 4; kk++)
                #pragma unroll
                for (int i = 0; i < 4; i++)
                    #pragma unroll
                    for (int j = 0; j < 4; j++)
                        oacc[i][j] += a_[i][kk] * b_[kk][j];
        }
    }

    __syncthreads();   // den finalized

    #pragma unroll
    for (int i = 0; i < 4; i++) {
        float inv = 1.0f / den[r + i];
        float4 o;
        o.x = oacc[i][0] * inv;
        o.y = oacc[i][1] * inv;
        o.z = oacc[i][2] * inv;
        o.w = oacc[i][3] * inv;
        *(float4*)(O + ((size_t)b * LQ + q0 + r + i) * DH + c) = o;
    }
}

extern "C" void kernel_launch(void* const* d_in, const int* in_sizes, int n_in,
                              void* d_out, int out_size) {
    // Identify the mask as the largest input; q,k,v are the rest in order.
    int mask_idx = 0;
    for (int i = 1; i < n_in; i++)
        if (in_sizes[i] > in_sizes[mask_idx]) mask_idx = i;

    const float* qkv[3];
    int nq = 0;
    for (int i = 0; i < n_in && nq < 3; i++)
        if (i != mask_idx) qkv[nq++] = (const float*)d_in[i];

    const float* q = qkv[0];
    const float* k = qkv[1];
    const float* v = qkv[2];
    const void*  m = d_in[mask_idx];
    float* o = (float*)d_out;

    const int B = in_sizes[mask_idx] / (LQ * LK);

    size_t smem = (size_t)(4 * BQ * DH) * sizeof(float)   // Qs,Kt,Vs,Ps
                + BQ * sizeof(float)                      // den
                + BQ * BK;                                // mask bytes
    static int smem_set = 0;
    if (!smem_set) {
        cudaFuncSetAttribute(attn_fp32_kernel,
                             cudaFuncAttributeMaxDynamicSharedMemorySize, (int)smem);
        smem_set = 1;
    }

    detect_mask_kernel<<<1, 1>>>((const unsigned int*)m);

    dim3 grid(LQ / BQ, B);
    attn_fp32_kernel<<<grid, NTHREADS, smem>>>(q, k, v, m, o);
}

// round 5
// speedup vs baseline: 1.7874x; 1.7874x over previous
#include <cuda_runtime.h>
#include <cuda_bf16.h>
#include <stdint.h>

// ScaledDotProductAttention (reference semantics, unstable exp):
//   s = (q·k)/8 ; s[mask]=0 ; e=exp(s) ; attn=e/rowsum(e) ; out=attn·v
// Masked slots contribute exp(0)=1; no max-subtraction -> streaming accumulation.
//
// Base-sm_100 implementation (tcgen05 unavailable: harness targets sm_100, not
// sm_100a). Uses warp-level mma.sync.m16n8k16 bf16 with split precision:
//   S  = Qh·Kh^T + Ql·Kh^T + Qh·Kl^T
//   O += Ph·Vh   + Pl·Vh   + Ph·Vl
// P fragments are built directly from S accumulators (no SMEM round trip).

#define LQ 2048
#define LK 2048
#define DH 64
#define BQ 128
#define BK 128
#define NTILES (LK / BK)
#define NTHREADS 256

#define TSTRIDE 144                    // bf16 tile row stride (bytes): conflict-free ldmatrix
#define TILE_BYTES (128 * TSTRIDE)     // 18432
#define SM_QH 0
#define SM_QL (SM_QH + TILE_BYTES)
#define SM_KH (SM_QL + TILE_BYTES)
#define SM_KL (SM_KH + TILE_BYTES)
#define SM_VH (SM_KL + TILE_BYTES)
#define SM_VL (SM_VH + TILE_BYTES)
#define MSTRIDE 136                    // mask row stride (bytes)
#define SM_MS (SM_VL + TILE_BYTES)
#define SM_TOTAL (SM_MS + 128 * MSTRIDE)

// =================== helpers ===================
__device__ __forceinline__ uint32_t smem_u32(const void* p) {
    uint32_t a;
    asm("{ .reg .u64 t; cvta.to.shared.u64 t, %1; cvt.u32.u64 %0, t; }" : "=r"(a) : "l"(p));
    return a;
}

__device__ __forceinline__ void ldsm_x4(uint32_t* r, uint32_t a) {
    asm volatile("ldmatrix.sync.aligned.m8n8.x4.shared.b16 {%0,%1,%2,%3}, [%4];"
                 : "=r"(r[0]), "=r"(r[1]), "=r"(r[2]), "=r"(r[3]) : "r"(a));
}
__device__ __forceinline__ void ldsm_x2(uint32_t* r, uint32_t a) {
    asm volatile("ldmatrix.sync.aligned.m8n8.x2.shared.b16 {%0,%1}, [%2];"
                 : "=r"(r[0]), "=r"(r[1]) : "r"(a));
}
__device__ __forceinline__ void ldsm_x2_t(uint32_t* r, uint32_t a) {
    asm volatile("ldmatrix.sync.aligned.m8n8.x2.trans.shared.b16 {%0,%1}, [%2];"
                 : "=r"(r[0]), "=r"(r[1]) : "r"(a));
}

__device__ __forceinline__ void mma16816(float* c, const uint32_t* a, const uint32_t* b) {
    asm volatile("mma.sync.aligned.m16n8k16.row.col.f32.bf16.bf16.f32 "
                 "{%0,%1,%2,%3}, {%4,%5,%6,%7}, {%8,%9}, {%0,%1,%2,%3};"
                 : "+f"(c[0]), "+f"(c[1]), "+f"(c[2]), "+f"(c[3])
                 : "r"(a[0]), "r"(a[1]), "r"(a[2]), "r"(a[3]), "r"(b[0]), "r"(b[1]));
}

// fp32 pair -> bf16x2 hi + bf16x2 lo residual
__device__ __forceinline__ void split_pair(uint32_t& hp, uint32_t& lp, float a, float b) {
    asm("cvt.rn.bf16x2.f32 %0, %1, %2;" : "=r"(hp) : "f"(b), "f"(a));   // lo16=a, hi16=b
    float ha = __uint_as_float(hp << 16);
    float hb = __uint_as_float(hp & 0xFFFF0000u);
    float ra = a - ha, rb = b - hb;
    asm("cvt.rn.bf16x2.f32 %0, %1, %2;" : "=r"(lp) : "f"(rb), "f"(ra));
}

// 128x64 fp32 gmem tile -> bf16 hi/lo SMEM tiles ([row][d], TSTRIDE bytes/row)
__device__ __forceinline__ void load_tile_split(const float* __restrict__ g, char* sm,
                                                int oh, int ol, int tid) {
    const int row = tid >> 1, d0 = (tid & 1) << 5;
    const float4* s4 = (const float4*)(g + (size_t)row * DH + d0);
    char* hrow = sm + oh + row * TSTRIDE + d0 * 2;
    char* lrow = sm + ol + row * TSTRIDE + d0 * 2;
    #pragma unroll
    for (int u = 0; u < 8; u++) {
        float4 f = s4[u];
        uint32_t h0, l0, h1, l1;
        split_pair(h0, l0, f.x, f.y);
        split_pair(h1, l1, f.z, f.w);
        *(uint32_t*)(hrow + 8 * u)     = h0;
        *(uint32_t*)(hrow + 8 * u + 4) = h1;
        *(uint32_t*)(lrow + 8 * u)     = l0;
        *(uint32_t*)(lrow + 8 * u + 4) = l1;
    }
}

// =================== mask encoding detection ===================
__device__ int g_mask_words;   // 0 = u8 bytes, 1 = 4-byte words (int32/float32)

__global__ void detect_mask_kernel(const unsigned int* __restrict__ m) {
    int words = 1;
    for (int i = 0; i < 4096; i++) {
        unsigned int w = m[i];
        if (w != 0u && w != 1u && w != 0x3F800000u) { words = 0; break; }
    }
    g_mask_words = words;
}

// =================== main kernel ===================
__global__ void __launch_bounds__(NTHREADS, 1)
attn_mma_kernel(const float* __restrict__ Q, const float* __restrict__ K,
                const float* __restrict__ V, const void* __restrict__ Mraw,
                float* __restrict__ O) {
    extern __shared__ char sm[];
    const uint32_t smb = smem_u32(sm);
    const int tid  = threadIdx.x;
    const int w    = tid >> 5;          // warp 0..7, owns q-rows w*16..w*16+15
    const int lane = tid & 31;
    const int g    = lane >> 2;         // row-in-8 group
    const int t4   = lane & 3;          // col pair selector

    const int b  = blockIdx.y;
    const int q0 = blockIdx.x * BQ;
    const int mask_words = g_mask_words;

    const float* Qb = Q + ((size_t)b * LQ + q0) * DH;
    const float* Kb = K + (size_t)b * LK * DH;
    const float* Vb = V + (size_t)b * LK * DH;
    const size_t mbase = ((size_t)b * LQ + q0) * (size_t)LK;

    // per-lane ldmatrix base addresses
    const uint32_t a_base = smb + (uint32_t)(w * 16 + (lane & 15)) * TSTRIDE + (lane >> 4) * 16;
    const uint32_t b_base = smb + (uint32_t)(lane & 7) * TSTRIDE + ((lane >> 3) & 1) * 16;
    const uint32_t v_base = smb + (uint32_t)(lane & 15) * TSTRIDE;
    // mask: rows (w*16+g), (w*16+g+8); col byte offset 2*t4 (+ ntile*8)
    const char* m_row0 = sm + SM_MS + (w * 16 + g) * MSTRIDE + 2 * t4;
    const char* m_row1 = m_row0 + 8 * MSTRIDE;

    // ---- Q tile: load + split once ----
    load_tile_split(Qb, sm, SM_QH, SM_QL, tid);

    float oacc[8][4];
    #pragma unroll
    for (int j = 0; j < 8; j++)
        #pragma unroll
        for (int i = 0; i < 4; i++) oacc[j][i] = 0.0f;
    float den0 = 0.0f, den1 = 0.0f;

    for (int t = 0; t < NTILES; t++) {
        __syncthreads();   // previous tile's compute (incl. PV reads) done

        // ---- load K/V (split bf16) + mask tile ----
        load_tile_split(Kb + (size_t)(t * BK) * DH, sm, SM_KH, SM_KL, tid);
        load_tile_split(Vb + (size_t)(t * BK) * DH, sm, SM_VH, SM_VL, tid);
        {
            const int qrow = tid >> 1;
            const int mc0  = (tid & 1) << 6;
            char* dst = sm + SM_MS + qrow * MSTRIDE + mc0;
            const size_t e = mbase + (size_t)qrow * LK + (size_t)t * BK + mc0;
            if (mask_words) {
                const uint4* src = (const uint4*)((const unsigned int*)Mraw + e);
                #pragma unroll
                for (int i = 0; i < 16; i++) {
                    uint4 mw = src[i];
                    uint32_t p = (mw.x ? 1u : 0u) | (mw.y ? 0x100u : 0u)
                               | (mw.z ? 0x10000u : 0u) | (mw.w ? 0x1000000u : 0u);
                    *(uint32_t*)(dst + 4 * i) = p;
                }
            } else {
                const uint32_t* src = (const uint32_t*)((const unsigned char*)Mraw + e);
                #pragma unroll
                for (int i = 0; i < 16; i++) *(uint32_t*)(dst + 4 * i) = src[i];
            }
        }
        __syncthreads();

        // ---- S = Qh·Kh + Ql·Kh + Qh·Kl  (per warp: 16 rows x 128 keys) ----
        float sacc[16][4];
        #pragma unroll
        for (int nt = 0; nt < 16; nt++)
            #pragma unroll
            for (int i = 0; i < 4; i++) sacc[nt][i] = 0.0f;

        #pragma unroll
        for (int kt = 0; kt < 4; kt++) {           // 16 d-elements per step
            uint32_t ah[4], al[4];
            ldsm_x4(ah, a_base + SM_QH + kt * 32);
            ldsm_x4(al, a_base + SM_QL + kt * 32);
            #pragma unroll
            for (int nt = 0; nt < 16; nt++) {
                uint32_t bh[2], bl[2];
                ldsm_x2(bh, b_base + SM_KH + nt * (8 * TSTRIDE) + kt * 32);
                ldsm_x2(bl, b_base + SM_KL + nt * (8 * TSTRIDE) + kt * 32);
                mma16816(sacc[nt], ah, bh);
                mma16816(sacc[nt], al, bh);
                mma16816(sacc[nt], ah, bl);
            }
        }

        // ---- epilogue + PV per 16-key group ----
        #pragma unroll
        for (int kt2 = 0; kt2 < 8; kt2++) {
            const int n0 = 2 * kt2, n1 = n0 + 1;
            uint16_t mA0 = *(const uint16_t*)(m_row0 + n0 * 8);
            uint16_t mB0 = *(const uint16_t*)(m_row1 + n0 * 8);
            uint16_t mA1 = *(const uint16_t*)(m_row0 + n1 * 8);
            uint16_t mB1 = *(const uint16_t*)(m_row1 + n1 * 8);

            float p00 = (mA0 & 0xFF) ? 1.0f : __expf(sacc[n0][0] * 0.125f);
            float p01 = (mA0 >> 8)   ? 1.0f : __expf(sacc[n0][1] * 0.125f);
            float p02 = (mB0 & 0xFF) ? 1.0f : __expf(sacc[n0][2] * 0.125f);
            float p03 = (mB0 >> 8)   ? 1.0f : __expf(sacc[n0][3] * 0.125f);
            float p10 = (mA1 & 0xFF) ? 1.0f : __expf(sacc[n1][0] * 0.125f);
            float p11 = (mA1 >> 8)   ? 1.0f : __expf(sacc[n1][1] * 0.125f);
            float p12 = (mB1 & 0xFF) ? 1.0f : __expf(sacc[n1][2] * 0.125f);
            float p13 = (mB1 >> 8)   ? 1.0f : __expf(sacc[n1][3] * 0.125f);

            den0 += p00 + p01 + p10 + p11;
            den1 += p02 + p03 + p12 + p13;

            uint32_t ph[4], pl[4];
            split_pair(ph[0], pl[0], p00, p01);    // P[g][2t,2t+1]   keys n0
            split_pair(ph[1], pl[1], p02, p03);    // P[g+8][2t,2t+1] keys n0
            split_pair(ph[2], pl[2], p10, p11);    // P[g][2t+8..]    keys n1
            split_pair(ph[3], pl[3], p12, p13);    // P[g+8][2t+8..]  keys n1

            const uint32_t vrow = v_base + kt2 * (16 * TSTRIDE);
            #pragma unroll
            for (int j = 0; j < 8; j++) {          // d-tiles of 8
                uint32_t vh[2], vl[2];
                ldsm_x2_t(vh, vrow + SM_VH + j * 16);
                ldsm_x2_t(vl, vrow + SM_VL + j * 16);
                mma16816(oacc[j], ph, vh);
                mma16816(oacc[j], pl, vh);
                mma16816(oacc[j], ph, vl);
            }
        }
    }

    // ---- reduce den across quad (lanes sharing rows) ----
    den0 += __shfl_xor_sync(0xFFFFFFFFu, den0, 1);
    den0 += __shfl_xor_sync(0xFFFFFFFFu, den0, 2);
    den1 += __shfl_xor_sync(0xFFFFFFFFu, den1, 1);
    den1 += __shfl_xor_sync(0xFFFFFFFFu, den1, 2);
    const float inv0 = 1.0f / den0;
    const float inv1 = 1.0f / den1;

    // ---- write output ----
    const int row0 = q0 + w * 16 + g;
    float* o0 = O + ((size_t)b * LQ + row0) * DH + 2 * t4;
    float* o1 = o0 + 8 * DH;
    #pragma unroll
    for (int j = 0; j < 8; j++) {
        float2 w0 = make_float2(oacc[j][0] * inv0, oacc[j][1] * inv0);
        float2 w1 = make_float2(oacc[j][2] * inv1, oacc[j][3] * inv1);
        *(float2*)(o0 + 8 * j) = w0;
        *(float2*)(o1 + 8 * j) = w1;
    }
}

extern "C" void kernel_launch(void* const* d_in, const int* in_sizes, int n_in,
                              void* d_out, int out_size) {
    int mask_idx = 0;
    for (int i = 1; i < n_in; i++)
        if (in_sizes[i] > in_sizes[mask_idx]) mask_idx = i;

    const float* qkv[3];
    int nq = 0;
    for (int i = 0; i < n_in && nq < 3; i++)
        if (i != mask_idx) qkv[nq++] = (const float*)d_in[i];

    const float* q = qkv[0];
    const float* k = qkv[1];
    const float* v = qkv[2];
    const void*  m = d_in[mask_idx];
    float* o = (float*)d_out;

    const int B = in_sizes[mask_idx] / (LQ * LK);

    static int smem_set = 0;
    if (!smem_set) {
        cudaFuncSetAttribute(attn_mma_kernel,
                             cudaFuncAttributeMaxDynamicSharedMemorySize, SM_TOTAL);
        smem_set = 1;
    }

    detect_mask_kernel<<<1, 1>>>((const unsigned int*)m);

    dim3 grid(LQ / BQ, B);
    attn_mma_kernel<<<grid, NTHREADS, SM_TOTAL>>>(q, k, v, m, o);
}

// round 8
// speedup vs baseline: 2.8118x; 1.5731x over previous
#include <cuda_runtime.h>
#include <cuda_bf16.h>
#include <stdint.h>

// ScaledDotProductAttention (reference semantics, unstable exp):
//   s = (q·k)/8 ; s[mask]=0 ; e=exp(s) ; attn=e/rowsum(e) ; out=attn·v
// Masked slots contribute exp(0)=1; no max-subtraction -> streaming accumulation.
//
// Base-sm_100 mma.sync.m16n8k16 bf16, split precision:
//   S  = Qh·Kh^T + Ql·Kh^T + Qh·Kl^T ;  O += Ph·Vh + Pl·Vh + Ph·Vl
// 2D warp tiling: 4 q-warps x 2 k-warps; cross-warp O/den reduction via SMEM.

#define LQ 2048
#define LK 2048
#define DH 64
#define BQ 128
#define BK 128
#define NTILES (LK / BK)
#define NTHREADS 256

#define TSTRIDE 144                    // bf16 tile row stride (bytes)
#define TILE_BYTES (128 * TSTRIDE)     // 18432
#define SM_QH 0
#define SM_QL (SM_QH + TILE_BYTES)
#define SM_KH (SM_QL + TILE_BYTES)
#define SM_KL (SM_KH + TILE_BYTES)
#define SM_VH (SM_KL + TILE_BYTES)
#define SM_VL (SM_VH + TILE_BYTES)
#define MSTRIDE 136
#define SM_MS (SM_VL + TILE_BYTES)
#define SM_DEN (SM_MS + 128 * MSTRIDE)     // den partials: [2][128] floats
#define SM_TOTAL (SM_DEN + 1024)
#define SM_OSM SM_KH                       // O partial buffer (reuses K tiles)
#define OSTRIDE 288                        // bytes per row (72 floats)

// =================== helpers ===================
__device__ __forceinline__ uint32_t smem_u32(const void* p) {
    uint32_t a;
    asm("{ .reg .u64 t; cvta.to.shared.u64 t, %1; cvt.u32.u64 %0, t; }" : "=r"(a) : "l"(p));
    return a;
}
__device__ __forceinline__ void ldsm_x4(uint32_t* r, uint32_t a) {
    asm volatile("ldmatrix.sync.aligned.m8n8.x4.shared.b16 {%0,%1,%2,%3}, [%4];"
                 : "=r"(r[0]), "=r"(r[1]), "=r"(r[2]), "=r"(r[3]) : "r"(a));
}
__device__ __forceinline__ void ldsm_x2(uint32_t* r, uint32_t a) {
    asm volatile("ldmatrix.sync.aligned.m8n8.x2.shared.b16 {%0,%1}, [%2];"
                 : "=r"(r[0]), "=r"(r[1]) : "r"(a));
}
__device__ __forceinline__ void ldsm_x2_t(uint32_t* r, uint32_t a) {
    asm volatile("ldmatrix.sync.aligned.m8n8.x2.trans.shared.b16 {%0,%1}, [%2];"
                 : "=r"(r[0]), "=r"(r[1]) : "r"(a));
}
__device__ __forceinline__ void mma16816(float* c, const uint32_t* a, const uint32_t* b) {
    asm volatile("mma.sync.aligned.m16n8k16.row.col.f32.bf16.bf16.f32 "
                 "{%0,%1,%2,%3}, {%4,%5,%6,%7}, {%8,%9}, {%0,%1,%2,%3};"
                 : "+f"(c[0]), "+f"(c[1]), "+f"(c[2]), "+f"(c[3])
                 : "r"(a[0]), "r"(a[1]), "r"(a[2]), "r"(a[3]), "r"(b[0]), "r"(b[1]));
}
__device__ __forceinline__ void split_pair(uint32_t& hp, uint32_t& lp, float a, float b) {
    asm("cvt.rn.bf16x2.f32 %0, %1, %2;" : "=r"(hp) : "f"(b), "f"(a));   // lo16=a, hi16=b
    float ha = __uint_as_float(hp << 16);
    float hb = __uint_as_float(hp & 0xFFFF0000u);
    float ra = a - ha, rb = b - hb;
    asm("cvt.rn.bf16x2.f32 %0, %1, %2;" : "=r"(lp) : "f"(rb), "f"(ra));
}
__device__ __forceinline__ void load_tile_split(const float* __restrict__ g, char* sm,
                                                int oh, int ol, int tid) {
    const int row = tid >> 1, d0 = (tid & 1) << 5;
    const float4* s4 = (const float4*)(g + (size_t)row * DH + d0);
    char* hrow = sm + oh + row * TSTRIDE + d0 * 2;
    char* lrow = sm + ol + row * TSTRIDE + d0 * 2;
    #pragma unroll
    for (int u = 0; u < 8; u++) {
        float4 f = s4[u];
        uint32_t h0, l0, h1, l1;
        split_pair(h0, l0, f.x, f.y);
        split_pair(h1, l1, f.z, f.w);
        *(uint32_t*)(hrow + 8 * u)     = h0;
        *(uint32_t*)(hrow + 8 * u + 4) = h1;
        *(uint32_t*)(lrow + 8 * u)     = l0;
        *(uint32_t*)(lrow + 8 * u + 4) = l1;
    }
}

// =================== mask encoding detection (parallel) ===================
__device__ int g_mask_words;   // 0 = u8 bytes, 1 = 4-byte words (int32/float32)

__global__ void detect_mask_kernel(const unsigned int* __restrict__ m) {
    __shared__ int bad;
    if (threadIdx.x == 0) bad = 0;
    __syncthreads();
    int ok = 1;
    for (int i = threadIdx.x; i < 4096; i += 256) {
        unsigned int w = m[i];
        if (w != 0u && w != 1u && w != 0x3F800000u) ok = 0;
    }
    if (!ok) bad = 1;        // benign race: same value
    __syncthreads();
    if (threadIdx.x == 0) g_mask_words = bad ? 0 : 1;
}

// =================== main kernel ===================
__global__ void __launch_bounds__(NTHREADS, 1)
attn_mma_kernel(const float* __restrict__ Q, const float* __restrict__ K,
                const float* __restrict__ V, const void* __restrict__ Mraw,
                float* __restrict__ O) {
    extern __shared__ char sm[];
    const uint32_t smb = smem_u32(sm);
    const int tid  = threadIdx.x;
    const int w    = tid >> 5;
    const int lane = tid & 31;
    const int wq   = w & 3;             // q block: rows wq*32 .. +31
    const int wk   = w >> 2;            // k half:  keys wk*64 .. +63
    const int g    = lane >> 2;
    const int t4   = lane & 3;

    const int b  = blockIdx.y;
    const int q0 = blockIdx.x * BQ;
    const int mask_words = g_mask_words;

    const float* Qb = Q + ((size_t)b * LQ + q0) * DH;
    const float* Kb = K + (size_t)b * LK * DH;
    const float* Vb = V + (size_t)b * LK * DH;
    const size_t mbase = ((size_t)b * LQ + q0) * (size_t)LK;

    // ldmatrix lane bases
    const uint32_t a_base = smb + (uint32_t)(wq * 32 + (lane & 15)) * TSTRIDE + (lane >> 4) * 16;
    const uint32_t b_base = smb + (uint32_t)(wk * 64 + (lane & 7)) * TSTRIDE + ((lane >> 3) & 1) * 16;
    const uint32_t v_base = smb + (uint32_t)(wk * 64 + (lane & 15)) * TSTRIDE;
    const char* m_row = sm + SM_MS + (wq * 32 + g) * MSTRIDE + wk * 64 + 2 * t4;

    // ---- Q tile: load + split once ----
    load_tile_split(Qb, sm, SM_QH, SM_QL, tid);

    float oacc[2][8][4];
    #pragma unroll
    for (int mt = 0; mt < 2; mt++)
        #pragma unroll
        for (int j = 0; j < 8; j++)
            #pragma unroll
            for (int i = 0; i < 4; i++) oacc[mt][j][i] = 0.0f;
    float den[2][2] = {{0.0f, 0.0f}, {0.0f, 0.0f}};   // [mt][row-half]

    for (int t = 0; t < NTILES; t++) {
        __syncthreads();

        load_tile_split(Kb + (size_t)(t * BK) * DH, sm, SM_KH, SM_KL, tid);
        load_tile_split(Vb + (size_t)(t * BK) * DH, sm, SM_VH, SM_VL, tid);
        {
            const int qrow = tid >> 1;
            const int mc0  = (tid & 1) << 6;
            char* dst = sm + SM_MS + qrow * MSTRIDE + mc0;
            const size_t e = mbase + (size_t)qrow * LK + (size_t)t * BK + mc0;
            if (mask_words) {
                const uint4* src = (const uint4*)((const unsigned int*)Mraw + e);
                #pragma unroll
                for (int i = 0; i < 16; i++) {
                    uint4 mw = src[i];
                    uint32_t p = (mw.x ? 1u : 0u) | (mw.y ? 0x100u : 0u)
                               | (mw.z ? 0x10000u : 0u) | (mw.w ? 0x1000000u : 0u);
                    *(uint32_t*)(dst + 4 * i) = p;
                }
            } else {
                const uint32_t* src = (const uint32_t*)((const unsigned char*)Mraw + e);
                #pragma unroll
                for (int i = 0; i < 16; i++) *(uint32_t*)(dst + 4 * i) = src[i];
            }
        }
        __syncthreads();

        // ---- S = Qh·Kh + Ql·Kh + Qh·Kl  (32 rows x 64 keys per warp) ----
        float sacc[2][8][4];
        #pragma unroll
        for (int mt = 0; mt < 2; mt++)
            #pragma unroll
            for (int nt = 0; nt < 8; nt++)
                #pragma unroll
                for (int i = 0; i < 4; i++) sacc[mt][nt][i] = 0.0f;

        #pragma unroll
        for (int kt = 0; kt < 4; kt++) {
            uint32_t ah[2][4], al[2][4];
            ldsm_x4(ah[0], a_base + SM_QH + kt * 32);
            ldsm_x4(ah[1], a_base + SM_QH + 16 * TSTRIDE + kt * 32);
            ldsm_x4(al[0], a_base + SM_QL + kt * 32);
            ldsm_x4(al[1], a_base + SM_QL + 16 * TSTRIDE + kt * 32);
            #pragma unroll
            for (int nt = 0; nt < 8; nt++) {
                uint32_t bh[2], bl[2];
                ldsm_x2(bh, b_base + SM_KH + nt * (8 * TSTRIDE) + kt * 32);
                ldsm_x2(bl, b_base + SM_KL + nt * (8 * TSTRIDE) + kt * 32);
                #pragma unroll
                for (int mt = 0; mt < 2; mt++) {
                    mma16816(sacc[mt][nt], ah[mt], bh);
                    mma16816(sacc[mt][nt], al[mt], bh);
                    mma16816(sacc[mt][nt], ah[mt], bl);
                }
            }
        }

        // ---- epilogue + PV per 16-key group (V frags hoisted across mt) ----
        #pragma unroll
        for (int kt2 = 0; kt2 < 4; kt2++) {
            uint32_t vfh[8][2], vfl[8][2];
            const uint32_t vrow = v_base + kt2 * (16 * TSTRIDE);
            #pragma unroll
            for (int j = 0; j < 8; j++) {
                ldsm_x2_t(vfh[j], vrow + SM_VH + j * 16);
                ldsm_x2_t(vfl[j], vrow + SM_VL + j * 16);
            }
            const int n0 = 2 * kt2, n1 = n0 + 1;
            #pragma unroll
            for (int mt = 0; mt < 2; mt++) {
                const char* mr0 = m_row + mt * (16 * MSTRIDE);
                const char* mr1 = mr0 + 8 * MSTRIDE;
                uint16_t mA0 = *(const uint16_t*)(mr0 + n0 * 8);
                uint16_t mB0 = *(const uint16_t*)(mr1 + n0 * 8);
                uint16_t mA1 = *(const uint16_t*)(mr0 + n1 * 8);
                uint16_t mB1 = *(const uint16_t*)(mr1 + n1 * 8);

                float p00 = (mA0 & 0xFF) ? 1.0f : __expf(sacc[mt][n0][0] * 0.125f);
                float p01 = (mA0 >> 8)   ? 1.0f : __expf(sacc[mt][n0][1] * 0.125f);
                float p02 = (mB0 & 0xFF) ? 1.0f : __expf(sacc[mt][n0][2] * 0.125f);
                float p03 = (mB0 >> 8)   ? 1.0f : __expf(sacc[mt][n0][3] * 0.125f);
                float p10 = (mA1 & 0xFF) ? 1.0f : __expf(sacc[mt][n1][0] * 0.125f);
                float p11 = (mA1 >> 8)   ? 1.0f : __expf(sacc[mt][n1][1] * 0.125f);
                float p12 = (mB1 & 0xFF) ? 1.0f : __expf(sacc[mt][n1][2] * 0.125f);
                float p13 = (mB1 >> 8)   ? 1.0f : __expf(sacc[mt][n1][3] * 0.125f);

                den[mt][0] += p00 + p01 + p10 + p11;
                den[mt][1] += p02 + p03 + p12 + p13;

                uint32_t ph[4], pl[4];
                split_pair(ph[0], pl[0], p00, p01);
                split_pair(ph[1], pl[1], p02, p03);
                split_pair(ph[2], pl[2], p10, p11);
                split_pair(ph[3], pl[3], p12, p13);

                #pragma unroll
                for (int j = 0; j < 8; j++) {
                    mma16816(oacc[mt][j], ph, vfh[j]);
                    mma16816(oacc[mt][j], pl, vfh[j]);
                    mma16816(oacc[mt][j], ph, vfl[j]);
                }
            }
        }
    }

    // ---- quad-reduce den, publish partials ----
    #pragma unroll
    for (int mt = 0; mt < 2; mt++)
        #pragma unroll
        for (int h = 0; h < 2; h++) {
            den[mt][h] += __shfl_xor_sync(0xFFFFFFFFu, den[mt][h], 1);
            den[mt][h] += __shfl_xor_sync(0xFFFFFFFFu, den[mt][h], 2);
        }
    float* den_s = (float*)(sm + SM_DEN);
    if (t4 == 0) {
        #pragma unroll
        for (int mt = 0; mt < 2; mt++) {
            den_s[wk * 128 + wq * 32 + mt * 16 + g]     = den[mt][0];
            den_s[wk * 128 + wq * 32 + mt * 16 + g + 8] = den[mt][1];
        }
    }
    __syncthreads();   // all PV reads of K/V SMEM done; den partials visible

    // ---- wk=1 warps publish O partials into reused K-tile SMEM ----
    if (wk == 1) {
        #pragma unroll
        for (int mt = 0; mt < 2; mt++) {
            const int r0 = wq * 32 + mt * 16 + g;
            char* base0 = sm + SM_OSM + r0 * OSTRIDE + 8 * t4;
            char* base1 = base0 + 8 * OSTRIDE;
            #pragma unroll
            for (int j = 0; j < 8; j++) {
                *(float2*)(base0 + j * 32) = make_float2(oacc[mt][j][0], oacc[mt][j][1]);
                *(float2*)(base1 + j * 32) = make_float2(oacc[mt][j][2], oacc[mt][j][3]);
            }
        }
    }
    __syncthreads();

    // ---- wk=0 warps combine + normalize + write ----
    if (wk == 0) {
        #pragma unroll
        for (int mt = 0; mt < 2; mt++) {
            const int r0 = wq * 32 + mt * 16 + g;
            const float inv0 = 1.0f / (den_s[r0] + den_s[128 + r0]);
            const float inv1 = 1.0f / (den_s[r0 + 8] + den_s[128 + r0 + 8]);
            const char* base0 = sm + SM_OSM + r0 * OSTRIDE + 8 * t4;
            const char* base1 = base0 + 8 * OSTRIDE;
            float* o0 = O + ((size_t)b * LQ + q0 + r0) * DH + 2 * t4;
            float* o1 = o0 + 8 * DH;
            #pragma unroll
            for (int j = 0; j < 8; j++) {
                float2 q0v = *(const float2*)(base0 + j * 32);
                float2 q1v = *(const float2*)(base1 + j * 32);
                *(float2*)(o0 + 8 * j) = make_float2((oacc[mt][j][0] + q0v.x) * inv0,
                                                     (oacc[mt][j][1] + q0v.y) * inv0);
                *(float2*)(o1 + 8 * j) = make_float2((oacc[mt][j][2] + q1v.x) * inv1,
                                                     (oacc[mt][j][3] + q1v.y) * inv1);
            }
        }
    }
}

extern "C" void kernel_launch(void* const* d_in, const int* in_sizes, int n_in,
                              void* d_out, int out_size) {
    int mask_idx = 0;
    for (int i = 1; i < n_in; i++)
        if (in_sizes[i] > in_sizes[mask_idx]) mask_idx = i;

    const float* qkv[3];
    int nq = 0;
    for (int i = 0; i < n_in && nq < 3; i++)
        if (i != mask_idx) qkv[nq++] = (const float*)d_in[i];

    const float* q = qkv[0];
    const float* k = qkv[1];
    const float* v = qkv[2];
    const void*  m = d_in[mask_idx];
    float* o = (float*)d_out;

    const int B = in_sizes[mask_idx] / (LQ * LK);

    cudaFuncSetAttribute(attn_mma_kernel,
                         cudaFuncAttributeMaxDynamicSharedMemorySize, SM_TOTAL);

    detect_mask_kernel<<<1, 256>>>((const unsigned int*)m);

    dim3 grid(LQ / BQ, B);
    attn_mma_kernel<<<grid, NTHREADS, SM_TOTAL>>>(q, k, v, m, o);
}

// round 9
// speedup vs baseline: 3.1489x; 1.1199x over previous
#include <cuda_runtime.h>
#include <cuda_bf16.h>
#include <stdint.h>

// ScaledDotProductAttention (reference semantics, unstable exp):
//   s = (q·k)/8 ; s[mask]=0 ; e=exp(s) ; attn=e/rowsum(e) ; out=attn·v
// Split-bf16 mma.sync pipeline, cp.async-staged K/V, exp2-prescaled Q.

#define LQ 2048
#define LK 2048
#define DH 64
#define BQ 128
#define BK 128
#define NTILES (LK / BK)
#define NTHREADS 256

#define QK_SCALE 0.18033688011112042f   // 0.125 * log2(e)

#define TSTRIDE 144                    // bf16 tile row stride (bytes)
#define TILE_BYTES (128 * TSTRIDE)     // 18432
#define SM_QH 0
#define SM_QL (SM_QH + TILE_BYTES)
#define SM_KH (SM_QL + TILE_BYTES)
#define SM_KL (SM_KH + TILE_BYTES)
#define SM_VH (SM_KL + TILE_BYTES)
#define SM_VL (SM_VH + TILE_BYTES)
#define MSTRIDE 136
#define SM_MS (SM_VL + TILE_BYTES)         // 110592, mask 128x136 = 17408
#define SM_DEN (SM_MS + 128 * MSTRIDE)     // 128000, den partials 1024B
#define STSTRIDE 272                       // fp32 staging row stride
#define SM_STK (SM_DEN + 1024)             // 129024, K staging 34816
#define SM_STV (SM_STK + 128 * STSTRIDE)   // 163840, V staging 34816
#define SM_TOTAL (SM_STV + 128 * STSTRIDE) // 198656
#define SM_OSM SM_KH                       // O partial buffer (reuses K tiles)
#define OSTRIDE 288

// =================== helpers ===================
__device__ __forceinline__ uint32_t smem_u32(const void* p) {
    uint32_t a;
    asm("{ .reg .u64 t; cvta.to.shared.u64 t, %1; cvt.u32.u64 %0, t; }" : "=r"(a) : "l"(p));
    return a;
}
__device__ __forceinline__ void ldsm_x4(uint32_t* r, uint32_t a) {
    asm volatile("ldmatrix.sync.aligned.m8n8.x4.shared.b16 {%0,%1,%2,%3}, [%4];"
                 : "=r"(r[0]), "=r"(r[1]), "=r"(r[2]), "=r"(r[3]) : "r"(a));
}
__device__ __forceinline__ void ldsm_x4_t(uint32_t* r, uint32_t a) {
    asm volatile("ldmatrix.sync.aligned.m8n8.x4.trans.shared.b16 {%0,%1,%2,%3}, [%4];"
                 : "=r"(r[0]), "=r"(r[1]), "=r"(r[2]), "=r"(r[3]) : "r"(a));
}
__device__ __forceinline__ void mma16816(float* c, const uint32_t* a, const uint32_t* b) {
    asm volatile("mma.sync.aligned.m16n8k16.row.col.f32.bf16.bf16.f32 "
                 "{%0,%1,%2,%3}, {%4,%5,%6,%7}, {%8,%9}, {%0,%1,%2,%3};"
                 : "+f"(c[0]), "+f"(c[1]), "+f"(c[2]), "+f"(c[3])
                 : "r"(a[0]), "r"(a[1]), "r"(a[2]), "r"(a[3]), "r"(b[0]), "r"(b[1]));
}
__device__ __forceinline__ float ex2f(float x) {
    float r;
    asm("ex2.approx.f32 %0, %1;" : "=f"(r) : "f"(x));
    return r;
}
__device__ __forceinline__ void split_pair(uint32_t& hp, uint32_t& lp, float a, float b) {
    asm("cvt.rn.bf16x2.f32 %0, %1, %2;" : "=r"(hp) : "f"(b), "f"(a));   // lo16=a, hi16=b
    float ha = __uint_as_float(hp << 16);
    float hb = __uint_as_float(hp & 0xFFFF0000u);
    float ra = a - ha, rb = b - hb;
    asm("cvt.rn.bf16x2.f32 %0, %1, %2;" : "=r"(lp) : "f"(rb), "f"(ra));
}

#define CP_ASYNC16(sm, gp) \
    asm volatile("cp.async.cg.shared.global [%0], [%1], 16;" :: "r"(sm), "l"(gp) : "memory")
#define CP_COMMIT() asm volatile("cp.async.commit_group;" ::: "memory")
#define CP_WAIT0()  asm volatile("cp.async.wait_group 0;" ::: "memory")

// gmem fp32 tile (128x64) -> raw fp32 staging via cp.async
__device__ __forceinline__ void stage_tile(const float* __restrict__ g,
                                           uint32_t st_base, int tid) {
    const int row = tid >> 1, h = tid & 1;
    const char* gp = (const char*)(g + (size_t)row * DH) + h * 16;
    const uint32_t sp = st_base + row * STSTRIDE + h * 16;
    #pragma unroll
    for (int u = 0; u < 8; u++) CP_ASYNC16(sp + u * 32, gp + u * 32);
}

// staging fp32 -> split bf16 hi/lo tiles
__device__ __forceinline__ void split_from_staging(const char* sm_ro, char* sm,
                                                   int st_off, int oh, int ol, int tid) {
    const int row = tid & 127, dh = tid >> 7;     // dh: d 0-31 / 32-63
    const float4* sp = (const float4*)(sm_ro + st_off + row * STSTRIDE + dh * 128);
    char* hrow = sm + oh + row * TSTRIDE + dh * 64;
    char* lrow = sm + ol + row * TSTRIDE + dh * 64;
    #pragma unroll
    for (int u = 0; u < 8; u++) {
        float4 f = sp[u];
        uint32_t h0, l0, h1, l1;
        split_pair(h0, l0, f.x, f.y);
        split_pair(h1, l1, f.z, f.w);
        *(uint2*)(hrow + 8 * u) = make_uint2(h0, h1);
        *(uint2*)(lrow + 8 * u) = make_uint2(l0, l1);
    }
}

// Q: direct gmem load with prescale, split to hi/lo
__device__ __forceinline__ void load_q_split(const float* __restrict__ g, char* sm, int tid) {
    const int row = tid >> 1, d0 = (tid & 1) << 5;
    const float4* s4 = (const float4*)(g + (size_t)row * DH + d0);
    char* hrow = sm + SM_QH + row * TSTRIDE + d0 * 2;
    char* lrow = sm + SM_QL + row * TSTRIDE + d0 * 2;
    #pragma unroll
    for (int u = 0; u < 8; u++) {
        float4 f = s4[u];
        f.x *= QK_SCALE; f.y *= QK_SCALE; f.z *= QK_SCALE; f.w *= QK_SCALE;
        uint32_t h0, l0, h1, l1;
        split_pair(h0, l0, f.x, f.y);
        split_pair(h1, l1, f.z, f.w);
        *(uint2*)(hrow + 8 * u) = make_uint2(h0, h1);
        *(uint2*)(lrow + 8 * u) = make_uint2(l0, l1);
    }
}

// =================== mask encoding detection (parallel) ===================
__device__ int g_mask_words;   // 0 = u8 bytes, 1 = 4-byte words

__global__ void detect_mask_kernel(const unsigned int* __restrict__ m) {
    __shared__ int bad;
    if (threadIdx.x == 0) bad = 0;
    __syncthreads();
    int ok = 1;
    for (int i = threadIdx.x; i < 4096; i += 256) {
        unsigned int w = m[i];
        if (w != 0u && w != 1u && w != 0x3F800000u) ok = 0;
    }
    if (!ok) bad = 1;
    __syncthreads();
    if (threadIdx.x == 0) g_mask_words = bad ? 0 : 1;
}

// =================== main kernel ===================
__global__ void __launch_bounds__(NTHREADS, 1)
attn_mma_kernel(const float* __restrict__ Q, const float* __restrict__ K,
                const float* __restrict__ V, const void* __restrict__ Mraw,
                float* __restrict__ O) {
    extern __shared__ char sm[];
    const uint32_t smb = smem_u32(sm);
    const int tid  = threadIdx.x;
    const int w    = tid >> 5;
    const int lane = tid & 31;
    const int wq   = w & 3;             // q block: rows wq*32 .. +31
    const int wk   = w >> 2;            // k half:  keys wk*64 .. +63
    const int g    = lane >> 2;
    const int t4   = lane & 3;

    const int b  = blockIdx.y;
    const int q0 = blockIdx.x * BQ;
    const int mask_words = g_mask_words;

    const float* Qb = Q + ((size_t)b * LQ + q0) * DH;
    const float* Kb = K + (size_t)b * LK * DH;
    const float* Vb = V + (size_t)b * LK * DH;
    const size_t mbase = ((size_t)b * LQ + q0) * (size_t)LK;

    // ldmatrix lane bases
    const uint32_t a_base  = smb + (uint32_t)(wq * 32 + (lane & 15)) * TSTRIDE + (lane >> 4) * 16;
    // K x4: groups (0-7: keys 0-7 b0) (8-15: keys 0-7 b1) (16-23: keys 8-15 b0) (24-31: keys 8-15 b1)
    const uint32_t b4_base = smb + (uint32_t)(wk * 64 + (lane & 7) + ((lane & 16) >> 1)) * TSTRIDE
                           + ((lane >> 3) & 1) * 16;
    // V x4 trans: groups (keys 0-7 col j) (keys 8-15 col j) (keys 0-7 col j+1) (keys 8-15 col j+1)
    const uint32_t v4_base = smb + (uint32_t)(wk * 64 + (lane & 15)) * TSTRIDE + (lane >> 4) * 16;
    const char* m_row = sm + SM_MS + (wq * 32 + g) * MSTRIDE + wk * 64 + 2 * t4;

    // ---- prologue: start staging tile 0, then Q split ----
    stage_tile(Kb, smb + SM_STK, tid);
    stage_tile(Vb, smb + SM_STV, tid);
    CP_COMMIT();

    load_q_split(Qb, sm, tid);

    float oacc[2][8][4];
    #pragma unroll
    for (int mt = 0; mt < 2; mt++)
        #pragma unroll
        for (int j = 0; j < 8; j++)
            #pragma unroll
            for (int i = 0; i < 4; i++) oacc[mt][j][i] = 0.0f;
    float den[2][2] = {{0.0f, 0.0f}, {0.0f, 0.0f}};

    for (int t = 0; t < NTILES; t++) {
        __syncthreads();   // previous tile's compute done (tiles + mask free)

        // ---- mask tile -> canonical u8 in SMEM ----
        {
            const int qrow = tid >> 1;
            const int mc0  = (tid & 1) << 6;
            char* dst = sm + SM_MS + qrow * MSTRIDE + mc0;
            const size_t e = mbase + (size_t)qrow * LK + (size_t)t * BK + mc0;
            if (mask_words) {
                const uint4* src = (const uint4*)((const unsigned int*)Mraw + e);
                #pragma unroll
                for (int i = 0; i < 16; i++) {
                    uint4 mw = src[i];
                    uint32_t p = (mw.x ? 1u : 0u) | (mw.y ? 0x100u : 0u)
                               | (mw.z ? 0x10000u : 0u) | (mw.w ? 0x1000000u : 0u);
                    *(uint32_t*)(dst + 4 * i) = p;
                }
            } else {
                const uint32_t* src = (const uint32_t*)((const unsigned char*)Mraw + e);
                #pragma unroll
                for (int i = 0; i < 16; i++) *(uint32_t*)(dst + 4 * i) = src[i];
            }
        }

        // ---- staging(t) ready -> split to bf16 tiles ----
        CP_WAIT0();
        __syncthreads();   // cross-thread staging visibility + mask STS done
        split_from_staging(sm, sm, SM_STK, SM_KH, SM_KL, tid);
        split_from_staging(sm, sm, SM_STV, SM_VH, SM_VL, tid);
        __syncthreads();   // tiles ready; staging fully drained

        // ---- start staging t+1 (hidden under compute) ----
        if (t + 1 < NTILES) {
            stage_tile(Kb + (size_t)((t + 1) * BK) * DH, smb + SM_STK, tid);
            stage_tile(Vb + (size_t)((t + 1) * BK) * DH, smb + SM_STV, tid);
            CP_COMMIT();
        }

        // ---- S = Qh·Kh + Ql·Kh + Qh·Kl  (32 rows x 64 keys per warp) ----
        float sacc[2][8][4];
        #pragma unroll
        for (int mt = 0; mt < 2; mt++)
            #pragma unroll
            for (int nt = 0; nt < 8; nt++)
                #pragma unroll
                for (int i = 0; i < 4; i++) sacc[mt][nt][i] = 0.0f;

        #pragma unroll
        for (int kt = 0; kt < 4; kt++) {
            uint32_t ah[2][4], al[2][4];
            ldsm_x4(ah[0], a_base + SM_QH + kt * 32);
            ldsm_x4(ah[1], a_base + SM_QH + 16 * TSTRIDE + kt * 32);
            ldsm_x4(al[0], a_base + SM_QL + kt * 32);
            ldsm_x4(al[1], a_base + SM_QL + 16 * TSTRIDE + kt * 32);
            #pragma unroll
            for (int nt2 = 0; nt2 < 4; nt2++) {
                uint32_t bh4[4], bl4[4];
                ldsm_x4(bh4, b4_base + SM_KH + nt2 * (16 * TSTRIDE) + kt * 32);
                ldsm_x4(bl4, b4_base + SM_KL + nt2 * (16 * TSTRIDE) + kt * 32);
                #pragma unroll
                for (int mt = 0; mt < 2; mt++) {
                    mma16816(sacc[mt][2 * nt2],     ah[mt], bh4);
                    mma16816(sacc[mt][2 * nt2],     al[mt], bh4);
                    mma16816(sacc[mt][2 * nt2],     ah[mt], bl4);
                    mma16816(sacc[mt][2 * nt2 + 1], ah[mt], bh4 + 2);
                    mma16816(sacc[mt][2 * nt2 + 1], al[mt], bh4 + 2);
                    mma16816(sacc[mt][2 * nt2 + 1], ah[mt], bl4 + 2);
                }
            }
        }

        // ---- epilogue + PV per 16-key group ----
        #pragma unroll
        for (int kt2 = 0; kt2 < 4; kt2++) {
            uint32_t vfh[16], vfl[16];
            const uint32_t vrow = v4_base + kt2 * (16 * TSTRIDE);
            #pragma unroll
            for (int jj = 0; jj < 4; jj++) {
                ldsm_x4_t(vfh + 4 * jj, vrow + SM_VH + jj * 32);
                ldsm_x4_t(vfl + 4 * jj, vrow + SM_VL + jj * 32);
            }
            const int n0 = 2 * kt2, n1 = n0 + 1;
            #pragma unroll
            for (int mt = 0; mt < 2; mt++) {
                const char* mr0 = m_row + mt * (16 * MSTRIDE);
                const char* mr1 = mr0 + 8 * MSTRIDE;
                uint16_t mA0 = *(const uint16_t*)(mr0 + n0 * 8);
                uint16_t mB0 = *(const uint16_t*)(mr1 + n0 * 8);
                uint16_t mA1 = *(const uint16_t*)(mr0 + n1 * 8);
                uint16_t mB1 = *(const uint16_t*)(mr1 + n1 * 8);

                float p00 = ex2f((mA0 & 0xFF) ? 0.0f : sacc[mt][n0][0]);
                float p01 = ex2f((mA0 >> 8)   ? 0.0f : sacc[mt][n0][1]);
                float p02 = ex2f((mB0 & 0xFF) ? 0.0f : sacc[mt][n0][2]);
                float p03 = ex2f((mB0 >> 8)   ? 0.0f : sacc[mt][n0][3]);
                float p10 = ex2f((mA1 & 0xFF) ? 0.0f : sacc[mt][n1][0]);
                float p11 = ex2f((mA1 >> 8)   ? 0.0f : sacc[mt][n1][1]);
                float p12 = ex2f((mB1 & 0xFF) ? 0.0f : sacc[mt][n1][2]);
                float p13 = ex2f((mB1 >> 8)   ? 0.0f : sacc[mt][n1][3]);

                den[mt][0] += p00 + p01 + p10 + p11;
                den[mt][1] += p02 + p03 + p12 + p13;

                uint32_t ph[4], pl[4];
                split_pair(ph[0], pl[0], p00, p01);
                split_pair(ph[1], pl[1], p02, p03);
                split_pair(ph[2], pl[2], p10, p11);
                split_pair(ph[3], pl[3], p12, p13);

                #pragma unroll
                for (int jj = 0; jj < 4; jj++) {
                    mma16816(oacc[mt][2 * jj],     ph, vfh + 4 * jj);
                    mma16816(oacc[mt][2 * jj],     pl, vfh + 4 * jj);
                    mma16816(oacc[mt][2 * jj],     ph, vfl + 4 * jj);
                    mma16816(oacc[mt][2 * jj + 1], ph, vfh + 4 * jj + 2);
                    mma16816(oacc[mt][2 * jj + 1], pl, vfh + 4 * jj + 2);
                    mma16816(oacc[mt][2 * jj + 1], ph, vfl + 4 * jj + 2);
                }
            }
        }
    }

    // ---- quad-reduce den, publish partials ----
    #pragma unroll
    for (int mt = 0; mt < 2; mt++)
        #pragma unroll
        for (int h = 0; h < 2; h++) {
            den[mt][h] += __shfl_xor_sync(0xFFFFFFFFu, den[mt][h], 1);
            den[mt][h] += __shfl_xor_sync(0xFFFFFFFFu, den[mt][h], 2);
        }
    float* den_s = (float*)(sm + SM_DEN);
    if (t4 == 0) {
        #pragma unroll
        for (int mt = 0; mt < 2; mt++) {
            den_s[wk * 128 + wq * 32 + mt * 16 + g]     = den[mt][0];
            den_s[wk * 128 + wq * 32 + mt * 16 + g + 8] = den[mt][1];
        }
    }
    __syncthreads();

    // ---- wk=1 warps publish O partials into reused K-tile SMEM ----
    if (wk == 1) {
        #pragma unroll
        for (int mt = 0; mt < 2; mt++) {
            const int r0 = wq * 32 + mt * 16 + g;
            char* base0 = sm + SM_OSM + r0 * OSTRIDE + 8 * t4;
            char* base1 = base0 + 8 * OSTRIDE;
            #pragma unroll
            for (int j = 0; j < 8; j++) {
                *(float2*)(base0 + j * 32) = make_float2(oacc[mt][j][0], oacc[mt][j][1]);
                *(float2*)(base1 + j * 32) = make_float2(oacc[mt][j][2], oacc[mt][j][3]);
            }
        }
    }
    __syncthreads();

    // ---- wk=0 warps combine + normalize + write ----
    if (wk == 0) {
        #pragma unroll
        for (int mt = 0; mt < 2; mt++) {
            const int r0 = wq * 32 + mt * 16 + g;
            const float inv0 = 1.0f / (den_s[r0] + den_s[128 + r0]);
            const float inv1 = 1.0f / (den_s[r0 + 8] + den_s[128 + r0 + 8]);
            const char* base0 = sm + SM_OSM + r0 * OSTRIDE + 8 * t4;
            const char* base1 = base0 + 8 * OSTRIDE;
            float* o0 = O + ((size_t)b * LQ + q0 + r0) * DH + 2 * t4;
            float* o1 = o0 + 8 * DH;
            #pragma unroll
            for (int j = 0; j < 8; j++) {
                float2 q0v = *(const float2*)(base0 + j * 32);
                float2 q1v = *(const float2*)(base1 + j * 32);
                *(float2*)(o0 + 8 * j) = make_float2((oacc[mt][j][0] + q0v.x) * inv0,
                                                     (oacc[mt][j][1] + q0v.y) * inv0);
                *(float2*)(o1 + 8 * j) = make_float2((oacc[mt][j][2] + q1v.x) * inv1,
                                                     (oacc[mt][j][3] + q1v.y) * inv1);
            }
        }
    }
}

extern "C" void kernel_launch(void* const* d_in, const int* in_sizes, int n_in,
                              void* d_out, int out_size) {
    int mask_idx = 0;
    for (int i = 1; i < n_in; i++)
        if (in_sizes[i] > in_sizes[mask_idx]) mask_idx = i;

    const float* qkv[3];
    int nq = 0;
    for (int i = 0; i < n_in && nq < 3; i++)
        if (i != mask_idx) qkv[nq++] = (const float*)d_in[i];

    const float* q = qkv[0];
    const float* k = qkv[1];
    const float* v = qkv[2];
    const void*  m = d_in[mask_idx];
    float* o = (float*)d_out;

    const int B = in_sizes[mask_idx] / (LQ * LK);

    cudaFuncSetAttribute(attn_mma_kernel,
                         cudaFuncAttributeMaxDynamicSharedMemorySize, SM_TOTAL);

    detect_mask_kernel<<<1, 256>>>((const unsigned int*)m);

    dim3 grid(LQ / BQ, B);
    attn_mma_kernel<<<grid, NTHREADS, SM_TOTAL>>>(q, k, v, m, o);
}